// round 9
// baseline (speedup 1.0000x reference)
#include <cuda_runtime.h>
#include <cstdint>

// MinArchitecture scan, 4 independent rows per thread, f32 math,
// cp.async smem pipeline (buffers in smem so ptxas can't demote them).
//   diff = h - x_t; t = tanh(d0*diff)
//   yh = c0 + c1*t + c2*t^2 ; s = 0.5 + 0.5*tanh(yh); h = x_t + s*diff

#define SEQ    512
#define BLOCK  64
#define IL     4
#define PITCH  132          // floats per thread: 4 rows * 32 + 4 pad (16x33B -> conflict-free)
#define NCHUNK (SEQ / 16)   // 32

__device__ __forceinline__ float tanh_fast(float x) {
    float y;
    asm("tanh.approx.f32 %0, %1;" : "=f"(y) : "f"(x));
    return y;
}

__global__ void __launch_bounds__(BLOCK) rnn_scan_kernel(
    const float* __restrict__ X,
    const float* __restrict__ W1,
    const float* __restrict__ W2,
    const float* __restrict__ bias,
    const float* __restrict__ Wz,
    const float* __restrict__ Ws,
    float* __restrict__ out)
{
    __shared__ float sbuf[BLOCK * PITCH];

    const int lt = threadIdx.x;
    const int tid = blockIdx.x * BLOCK + lt;
    const size_t r0 = (size_t)tid * IL;

    // ----- uniform scalar constants -----
    const float a1 = 1.0f / (1.0f + expf(W1[1] - W1[0]));
    const float a2 = 1.0f / (1.0f + expf(W2[1] - W2[0]));
    const float d0 = a1 - a2;
    const float wz = Wz[0];
    const float ws = Ws[0];
    const float b  = bias[0];
    const float c0 = 0.5f * (b + wz);
    const float c1 = 0.5f * ws;
    const float c2 = -wz;

    float* my = sbuf + lt * PITCH;   // row i: [i*32 .. i*32+15]=A, [i*32+16 .. i*32+31]=B

    uint32_t sb;
    {
        uint64_t tmp;
        asm("cvta.to.shared.u64 %0, %1;" : "=l"(tmp) : "l"(my));
        sb = (uint32_t)tmp;
    }

    const float* rows[IL];
    #pragma unroll
    for (int i = 0; i < IL; ++i) rows[i] = X + (r0 + i) * SEQ;

    // issue one 16-float chunk for all IL rows into half (0=A, 1=B); one group
#define ISSUE(half, c) do {                                                   \
        _Pragma("unroll")                                                     \
        for (int i = 0; i < IL; ++i) {                                        \
            _Pragma("unroll")                                                 \
            for (int j = 0; j < 4; ++j) {                                     \
                asm volatile("cp.async.cg.shared.global [%0], [%1], 16;"      \
                    :: "r"(sb + (unsigned)((i * 32 + (half) * 16 + j * 4) * 4)), \
                       "l"(rows[i] + (c) * 16 + j * 4) : "memory");           \
            }                                                                 \
        }                                                                     \
        asm volatile("cp.async.commit_group;" ::: "memory");                  \
    } while (0)

#define WAIT1() asm volatile("cp.async.wait_group 1;" ::: "memory")
#define WAIT0() asm volatile("cp.async.wait_group 0;" ::: "memory")

    float h[IL];

#define STEP(i, XT) do {                                      \
        float diff = h[i] - (XT);                             \
        float tt   = tanh_fast(d0 * diff);                    \
        float yh   = fmaf(fmaf(c2, tt, c1), tt, c0);          \
        float s    = fmaf(0.5f, tanh_fast(yh), 0.5f);         \
        h[i]       = fmaf(s, diff, (XT));                     \
    } while (0)

    // 16 interleaved steps over all IL rows from smem half
#define PROC(half, E0) do {                                                   \
        _Pragma("unroll")                                                     \
        for (int q = 0; q < 4; ++q) {                                         \
            float4 v[IL];                                                     \
            _Pragma("unroll")                                                 \
            for (int i = 0; i < IL; ++i)                                      \
                v[i] = *reinterpret_cast<const float4*>(                      \
                           my + i * 32 + (half) * 16 + q * 4);                \
            if (q > 0 || (E0) <= 0) {                                         \
                _Pragma("unroll")                                             \
                for (int i = 0; i < IL; ++i) STEP(i, v[i].x);                 \
            }                                                                 \
            if (q > 0 || (E0) <= 1) {                                         \
                _Pragma("unroll")                                             \
                for (int i = 0; i < IL; ++i) STEP(i, v[i].y);                 \
            }                                                                 \
            if (q > 0 || (E0) <= 2) {                                         \
                _Pragma("unroll")                                             \
                for (int i = 0; i < IL; ++i) STEP(i, v[i].z);                 \
            }                                                                 \
            _Pragma("unroll")                                                 \
            for (int i = 0; i < IL; ++i) STEP(i, v[i].w);                     \
        }                                                                     \
    } while (0)

    // prologue: chunk0 -> A, chunk1 -> B
    ISSUE(0, 0);
    ISSUE(1, 1);

    WAIT1();                              // chunk 0 resident
    #pragma unroll
    for (int i = 0; i < IL; ++i) h[i] = my[i * 32];   // h0 = X[:, 0]
    PROC(0, 1);                           // chunk 0, skip element 0

    // chunks 1..30
    #pragma unroll 1
    for (int c = 2; c < NCHUNK; c += 2) {
        ISSUE(0, c);                      // prefetch chunk c -> A
        WAIT1();                          // chunk c-1 (B) resident
        PROC(1, 0);                       // process chunk c-1
        ISSUE(1, c + 1);                  // prefetch chunk c+1 -> B (max 31)
        WAIT1();                          // chunk c (A) resident
        PROC(0, 0);                       // process chunk c
    }

    // final chunk 31 (in B)
    WAIT0();
    PROC(1, 0);

    // 4 consecutive outputs, r0 is 4-aligned -> float4 store
    float4 o;
    o.x = h[0]; o.y = h[1]; o.z = h[2]; o.w = h[3];
    *reinterpret_cast<float4*>(out + r0) = o;
}

extern "C" void kernel_launch(void* const* d_in, const int* in_sizes, int n_in,
                              void* d_out, int out_size)
{
    const float* X    = (const float*)d_in[0];
    const float* W1   = (const float*)d_in[1];
    const float* W2   = (const float*)d_in[2];
    const float* bias = (const float*)d_in[3];
    const float* Wz   = (const float*)d_in[4];
    const float* Ws   = (const float*)d_in[5];
    float* out = (float*)d_out;

    const int batch = out_size;                               // 65536
    const int grid  = (batch + IL * BLOCK - 1) / (IL * BLOCK);  // 256
    rnn_scan_kernel<<<grid, BLOCK>>>(X, W1, W2, bias, Wz, Ws, out);
}

// round 10
// speedup vs baseline: 1.1854x; 1.1854x over previous
#include <cuda_runtime.h>
#include <cstdint>

// MinArchitecture scan, 1 row/thread, smem-LUT gate (no MUFU in the chain).
// u-space recurrence:  u_{t+1} = G(u_t)*u_t + (xs_t - xs_{t+1}),  xs = d0*x
// seed u=0, xsprev=xs_0 makes the loop uniform (G(0)*0 + xs_0-xs_1 = u_1).
// out = (xs_511 + G(u_511)*u_511) / d0

#define SEQ     512
#define BLOCK   64
#define PITCH   36           // floats/thread in pipeline smem (16x36B, conflict-free)
#define NCHUNK  (SEQ / 16)   // 32
#define LUTN    2048
#define LSCALE  64.0f        // entries per unit of u; range [-16, 16)
#define LOFF    1024.0f
#define MAGIC   8388608.0f   // 2^23

__device__ __forceinline__ unsigned hfma2u(unsigned a, unsigned b, unsigned c) {
    unsigned r;
    asm("fma.rn.f16x2 %0, %1, %2, %3;" : "=r"(r) : "r"(a), "r"(b), "r"(c));
    return r;
}
__device__ __forceinline__ unsigned f2h2(float lo, float hi) {
    unsigned r;
    asm("cvt.rn.f16x2.f32 %0, %2, %1;" : "=r"(r) : "f"(lo), "f"(hi));
    return r;
}
// f16 in [0, ~1] (low half of u) -> f32; sign/denormal-safe for our s range
#define H2F_LO(u) __uint_as_float((((u) << 13) & 0x0FFFE000u) | 0x38000000u)

__global__ void __launch_bounds__(BLOCK) rnn_scan_kernel(
    const float* __restrict__ X,
    const float* __restrict__ W1,
    const float* __restrict__ W2,
    const float* __restrict__ bias,
    const float* __restrict__ Wz,
    const float* __restrict__ Ws,
    float* __restrict__ out)
{
    __shared__ float    sbuf[BLOCK * PITCH];
    __shared__ unsigned lut[LUTN];

    const int lt = threadIdx.x;
    const int r  = blockIdx.x * BLOCK + lt;

    // ----- uniform scalar constants -----
    const float a1 = 1.0f / (1.0f + expf(W1[1] - W1[0]));
    const float a2 = 1.0f / (1.0f + expf(W2[1] - W2[0]));
    float d0 = a1 - a2;
    if (fabsf(d0) < 1e-20f) d0 = 1e-20f;     // u-space exactly linear in d0
    const float rec = 1.0f / d0;
    const float wz = Wz[0];
    const float ws = Ws[0];
    const float b  = bias[0];
    const float c0 = 0.5f * (b + wz);
    const float c1 = 0.5f * ws;
    const float c2 = -wz;

    // ----- build LUT: G(u) sampled at u_i = (i - 1024)/64, f32 scratch in sbuf -----
    for (int i = lt; i < LUTN; i += BLOCK) {
        float u = ((float)i - LOFF) * (1.0f / LSCALE);
        float t = tanhf(u);
        float y = c0 + c1 * t + c2 * t * t;
        sbuf[i] = 0.5f + 0.5f * tanhf(y);
    }
    __syncthreads();
    for (int i = lt; i < LUTN; i += BLOCK) {
        float gm = sbuf[i > 0 ? i - 1 : 0];
        float gc = sbuf[i];
        float gp = sbuf[i < LUTN - 1 ? i + 1 : LUTN - 1];
        lut[i] = f2h2(gc, 0.5f * (gp - gm));   // lo = g, hi = central slope
    }
    __syncthreads();

    // ----- cp.async pipeline (R7 skeleton) -----
    const float* row = X + (size_t)r * SEQ;
    float* my = sbuf + lt * PITCH;             // [0..15] = A, [16..31] = B

    uint32_t sb;
    {
        uint64_t tmp;
        asm("cvta.to.shared.u64 %0, %1;" : "=l"(tmp) : "l"(my));
        sb = (uint32_t)tmp;
    }

#define ISSUE(half, c) do {                                                  \
        _Pragma("unroll")                                                    \
        for (int j = 0; j < 4; ++j) {                                        \
            asm volatile("cp.async.cg.shared.global [%0], [%1], 16;"         \
                         :: "r"(sb + (unsigned)(((half) * 16 + j * 4) * 4)), \
                            "l"(row + (c) * 16 + j * 4) : "memory");         \
        }                                                                    \
        asm volatile("cp.async.commit_group;" ::: "memory");                 \
    } while (0)
#define WAIT1() asm volatile("cp.async.wait_group 1;" ::: "memory")
#define WAIT0() asm volatile("cp.async.wait_group 0;" ::: "memory")

    float uv = 0.0f;     // u state
    float xsprev;        // d0 * x_t (previous element, scaled)

    // one scan step consuming raw element XF (= x_{t+1})
#define STEP(XF) do {                                              \
        float xscur = d0 * (XF);                                   \
        float yv    = fmaf(uv, LSCALE, MAGIC + LOFF);              \
        unsigned e  = lut[__float_as_uint(yv) & (LUTN - 1)];       \
        float rv    = yv - MAGIC;                                  \
        float frac  = fmaf(uv, LSCALE, LOFF - rv);                 \
        unsigned f2 = f2h2(frac, 0.0f);                            \
        unsigned s2 = hfma2u(e >> 16, f2, e);                      \
        float s     = H2F_LO(s2);                                  \
        uv = fmaf(s, uv, xsprev - xscur);                          \
        xsprev = xscur;                                            \
    } while (0)

#define PROC(half, E0) do {                                                 \
        _Pragma("unroll")                                                   \
        for (int q = 0; q < 4; ++q) {                                       \
            float4 v = *reinterpret_cast<const float4*>(my + (half) * 16 + q * 4); \
            if (q > 0 || (E0) <= 0) STEP(v.x);                              \
            if (q > 0 || (E0) <= 1) STEP(v.y);                              \
            if (q > 0 || (E0) <= 2) STEP(v.z);                              \
            STEP(v.w);                                                      \
        }                                                                   \
    } while (0)

    ISSUE(0, 0);
    ISSUE(1, 1);

    WAIT1();                       // chunk 0 resident
    xsprev = d0 * my[0];           // xs_0; uv = 0 seeds u_1 on first STEP
    PROC(0, 1);                    // consume x_1 .. x_15

    #pragma unroll 1
    for (int c = 2; c < NCHUNK; c += 2) {
        ISSUE(0, c);               // prefetch chunk c -> A
        WAIT1();                   // chunk c-1 (B) resident
        PROC(1, 0);
        ISSUE(1, c + 1);           // prefetch chunk c+1 -> B (max 31)
        WAIT1();                   // chunk c (A) resident
        PROC(0, 0);
    }

    WAIT0();
    PROC(1, 0);                    // chunk 31: consume .. x_511

    // final gate s_511 = G(u_511); out = (xs_511 + s*u) / d0
    {
        float yv    = fmaf(uv, LSCALE, MAGIC + LOFF);
        unsigned e  = lut[__float_as_uint(yv) & (LUTN - 1)];
        float rv    = yv - MAGIC;
        float frac  = fmaf(uv, LSCALE, LOFF - rv);
        unsigned f2 = f2h2(frac, 0.0f);
        unsigned s2 = hfma2u(e >> 16, f2, e);
        float s     = H2F_LO(s2);
        out[r] = rec * fmaf(s, uv, xsprev);
    }
}

extern "C" void kernel_launch(void* const* d_in, const int* in_sizes, int n_in,
                              void* d_out, int out_size)
{
    const float* X    = (const float*)d_in[0];
    const float* W1   = (const float*)d_in[1];
    const float* W2   = (const float*)d_in[2];
    const float* bias = (const float*)d_in[3];
    const float* Wz   = (const float*)d_in[4];
    const float* Ws   = (const float*)d_in[5];
    float* out = (float*)d_out;

    const int batch = out_size;                    // 65536
    const int grid  = (batch + BLOCK - 1) / BLOCK; // 1024
    rnn_scan_kernel<<<grid, BLOCK>>>(X, W1, W2, bias, Wz, Ws, out);
}

// round 11
// speedup vs baseline: 1.2412x; 1.0471x over previous
#include <cuda_runtime.h>
#include <cstdint>

// MinArchitecture scan, 1 row/thread, f32 smem-LUT gate, conversion-free chain.
// u-space recurrence:  u_{t+1} = G(u_t)*u_t + (xs_t - xs_{t+1}),  xs = d0*x
// G(u) = 0.5 + 0.5*tanh(c0 + c1*tanh(u) + c2*tanh(u)^2)
// seed u=0, xsprev=xs_0; out = (xs_511 + G(u_511)*u_511) / d0

#define SEQ     512
#define BLOCK   64
#define PITCH   36           // floats/thread in pipeline smem (16x36B, conflict-free)
#define NCHUNK  (SEQ / 16)   // 32
#define LUTN    2048
#define LSCALE  64.0f        // entries per unit of u; u range [-16, 16)
#define LOFF    1024.0f
#define MAGIC   8388608.0f   // 2^23

__global__ void __launch_bounds__(BLOCK) rnn_scan_kernel(
    const float* __restrict__ X,
    const float* __restrict__ W1,
    const float* __restrict__ W2,
    const float* __restrict__ bias,
    const float* __restrict__ Wz,
    const float* __restrict__ Ws,
    float* __restrict__ out)
{
    __shared__ float  sbuf[BLOCK * PITCH];
    __shared__ float2 lut[LUTN];           // (g, central slope), f32

    const int lt = threadIdx.x;
    const int r  = blockIdx.x * BLOCK + lt;

    // ----- uniform scalar constants -----
    const float a1 = 1.0f / (1.0f + expf(W1[1] - W1[0]));
    const float a2 = 1.0f / (1.0f + expf(W2[1] - W2[0]));
    float d0 = a1 - a2;
    if (fabsf(d0) < 1e-20f) d0 = 1e-20f;   // u-space exactly linear in d0
    const float rec = 1.0f / d0;
    const float wz = Wz[0];
    const float ws = Ws[0];
    const float b  = bias[0];
    const float c0 = 0.5f * (b + wz);
    const float c1 = 0.5f * ws;
    const float c2 = -wz;

    // ----- build LUT (accurate tanhf); f32 scratch in sbuf (2304 >= 2048) -----
    for (int i = lt; i < LUTN; i += BLOCK) {
        float u = ((float)i - LOFF) * (1.0f / LSCALE);
        float t = tanhf(u);
        float y = c0 + c1 * t + c2 * t * t;
        sbuf[i] = 0.5f + 0.5f * tanhf(y);
    }
    __syncthreads();
    for (int i = lt; i < LUTN; i += BLOCK) {
        float gm = sbuf[i > 0 ? i - 1 : 0];
        float gc = sbuf[i];
        float gp = sbuf[i < LUTN - 1 ? i + 1 : LUTN - 1];
        float2 e; e.x = gc; e.y = 0.5f * (gp - gm);
        lut[i] = e;
    }
    __syncthreads();

    // ----- cp.async pipeline (R7 skeleton) -----
    const float* row = X + (size_t)r * SEQ;
    float* my = sbuf + lt * PITCH;         // [0..15] = A, [16..31] = B

    uint32_t sb;
    {
        uint64_t tmp;
        asm("cvta.to.shared.u64 %0, %1;" : "=l"(tmp) : "l"(my));
        sb = (uint32_t)tmp;
    }

#define ISSUE(half, c) do {                                                  \
        _Pragma("unroll")                                                    \
        for (int j = 0; j < 4; ++j) {                                        \
            asm volatile("cp.async.cg.shared.global [%0], [%1], 16;"         \
                         :: "r"(sb + (unsigned)(((half) * 16 + j * 4) * 4)), \
                            "l"(row + (c) * 16 + j * 4) : "memory");         \
        }                                                                    \
        asm volatile("cp.async.commit_group;" ::: "memory");                 \
    } while (0)
#define WAIT1() asm volatile("cp.async.wait_group 1;" ::: "memory")
#define WAIT0() asm volatile("cp.async.wait_group 0;" ::: "memory")

    float uv = 0.0f;     // u state
    float xsprev;        // d0 * x_t (previous element, scaled)

    // one scan step consuming raw element XF (= x_{t+1})
    // chain: FFMA(yv) -> addr -> LDS.64 -> FFMA(s) -> FFMA(uv'); rest in shadow
#define STEP(XF) do {                                              \
        float xscur = d0 * (XF);                                   \
        float yv    = fmaf(uv, LSCALE, MAGIC + LOFF);              \
        float2 e    = lut[__float_as_uint(yv) & (LUTN - 1)];       \
        float rv    = yv - MAGIC;                                  \
        float frac  = fmaf(uv, LSCALE, LOFF - rv);                 \
        float s     = fmaf(e.y, frac, e.x);                        \
        uv = fmaf(s, uv, xsprev - xscur);                          \
        xsprev = xscur;                                            \
    } while (0)

#define PROC(half, E0) do {                                                 \
        _Pragma("unroll")                                                   \
        for (int q = 0; q < 4; ++q) {                                       \
            float4 v = *reinterpret_cast<const float4*>(my + (half) * 16 + q * 4); \
            if (q > 0 || (E0) <= 0) STEP(v.x);                              \
            if (q > 0 || (E0) <= 1) STEP(v.y);                              \
            if (q > 0 || (E0) <= 2) STEP(v.z);                              \
            STEP(v.w);                                                      \
        }                                                                   \
    } while (0)

    ISSUE(0, 0);
    ISSUE(1, 1);

    WAIT1();                       // chunk 0 resident
    xsprev = d0 * my[0];           // xs_0; uv = 0 seeds u_1 on first STEP
    PROC(0, 1);                    // consume x_1 .. x_15

    #pragma unroll 1
    for (int c = 2; c < NCHUNK; c += 2) {
        ISSUE(0, c);               // prefetch chunk c -> A
        WAIT1();                   // chunk c-1 (B) resident
        PROC(1, 0);
        ISSUE(1, c + 1);           // prefetch chunk c+1 -> B (max 31)
        WAIT1();                   // chunk c (A) resident
        PROC(0, 0);
    }

    WAIT0();
    PROC(1, 0);                    // chunk 31: consume .. x_511

    // final gate s_511 = G(u_511); out = (xs_511 + s*u) / d0
    {
        float yv   = fmaf(uv, LSCALE, MAGIC + LOFF);
        float2 e   = lut[__float_as_uint(yv) & (LUTN - 1)];
        float rv   = yv - MAGIC;
        float frac = fmaf(uv, LSCALE, LOFF - rv);
        float s    = fmaf(e.y, frac, e.x);
        out[r] = rec * fmaf(s, uv, xsprev);
    }
}

extern "C" void kernel_launch(void* const* d_in, const int* in_sizes, int n_in,
                              void* d_out, int out_size)
{
    const float* X    = (const float*)d_in[0];
    const float* W1   = (const float*)d_in[1];
    const float* W2   = (const float*)d_in[2];
    const float* bias = (const float*)d_in[3];
    const float* Wz   = (const float*)d_in[4];
    const float* Ws   = (const float*)d_in[5];
    float* out = (float*)d_out;

    const int batch = out_size;                    // 65536
    const int grid  = (batch + BLOCK - 1) / BLOCK; // 1024
    rnn_scan_kernel<<<grid, BLOCK>>>(X, W1, W2, bias, Wz, Ws, out);
}